// round 15
// baseline (speedup 1.0000x reference)
#include <cuda_runtime.h>

// Problem constants (fixed by the reference setup)
#define LSEQ   768
#define BATCH  2
#define N_MSA  4
#define DM     128
#define NREL   63   // 2*MAX_LEN - 1

// Scratch tables (device globals — no allocation allowed)
__device__ float g_Ptab[5][DM];   // masked_emb[t] @ W_proj[:64, :]
__device__ float g_Qtab[5][DM];   // masked_emb[t] @ W_proj[64:, :]
__device__ float g_R[NREL][DM];   // W_pos[r] + b_proj + b_pos

// ---------------------------------------------------------------------------
// Table setup: 68 tiny blocks. Blocks 0..4 -> Ptab/Qtab row t,
// blocks 5..67 -> R row (blockIdx-5).
// ---------------------------------------------------------------------------
__global__ void setup_kernel(const float* __restrict__ emb,
                             const float* __restrict__ W_proj,
                             const float* __restrict__ b_proj,
                             const float* __restrict__ W_pos,
                             const float* __restrict__ b_pos) {
    int d = threadIdx.x;          // 0..127
    int task = blockIdx.x;
    if (task < 5) {
        int t = task;
        float pt = 0.f, qt = 0.f;
        if (t != 0) {             // token 0 is masked to zero
            #pragma unroll 16
            for (int k = 0; k < 64; k++) {
                float ek = emb[t * 64 + k];
                pt = fmaf(ek, W_proj[k * DM + d], pt);
                qt = fmaf(ek, W_proj[(64 + k) * DM + d], qt);
            }
        }
        g_Ptab[t][d] = pt;
        g_Qtab[t][d] = qt;
    } else {
        int r = task - 5;
        g_R[r][d] = W_pos[r * DM + d] + b_proj[d] + b_pos[d];
    }
}

// Select one of 5 float4 table entries by token id (0..4) with select chains.
__device__ __forceinline__ float4 sel5(int sj, float4 t0, float4 t1, float4 t2,
                                       float4 t3, float4 t4) {
    bool a = (sj < 2), b0 = (sj == 0), c2 = (sj == 2), c3 = (sj == 3);
    float4 v;
    v.x = a ? (b0 ? t0.x : t1.x) : (c2 ? t2.x : (c3 ? t3.x : t4.x));
    v.y = a ? (b0 ? t0.y : t1.y) : (c2 ? t2.y : (c3 ? t3.y : t4.y));
    v.z = a ? (b0 ? t0.z : t1.z) : (c2 ? t2.z : (c3 ? t3.z : t4.z));
    v.w = a ? (b0 ? t0.w : t1.w) : (c2 ? t2.w : (c3 ? t3.w : t4.w));
    return v;
}

// Hot loop for a saturated-rel region: table in registers, tokens fetched
// 4-at-a-time with one LDS.U32 (s_seq is 4B-aligned); 4 back-to-back
// sel+STG.128 per iteration. Head/tail handle region misalignment.
__device__ __forceinline__ void run_reg(int jb, int je, const float4* __restrict__ tab,
                                        const unsigned char* __restrict__ s_seq,
                                        float4* __restrict__ outp, int lane) {
    if (jb >= je) return;
    float4 t0 = tab[0 * 32 + lane];
    float4 t1 = tab[1 * 32 + lane];
    float4 t2 = tab[2 * 32 + lane];
    float4 t3 = tab[3 * 32 + lane];
    float4 t4 = tab[4 * 32 + lane];

    int j = jb;
    // unaligned head (<=3 rows)
    for (; j < je && (j & 3); ++j) {
        float4 v = sel5(s_seq[j], t0, t1, t2, t3, t4);
        __stcs(&outp[(size_t)j * 32 + lane], v);
    }
    // 4-wide body
    const unsigned int* seq32 = (const unsigned int*)s_seq;
    for (; j + 3 < je; j += 4) {
        unsigned int w = seq32[j >> 2];                  // 4 token bytes
        float4 v0 = sel5((int)( w        & 0xFF), t0, t1, t2, t3, t4);
        float4 v1 = sel5((int)((w >>  8) & 0xFF), t0, t1, t2, t3, t4);
        float4 v2 = sel5((int)((w >> 16) & 0xFF), t0, t1, t2, t3, t4);
        float4 v3 = sel5((int)( w >> 24        ), t0, t1, t2, t3, t4);
        float4* p = &outp[(size_t)j * 32 + lane];
        __stcs(p,      v0);
        __stcs(p + 32, v1);
        __stcs(p + 64, v2);
        __stcs(p + 96, v3);
    }
    // tail (<=3 rows)
    for (; j < je; ++j) {
        float4 v = sel5(s_seq[j], t0, t1, t2, t3, t4);
        __stcs(&outp[(size_t)j * 32 + lane], v);
    }
}

// ---------------------------------------------------------------------------
// Main kernel: one block per (b, i). Each warp owns a CONTIGUOUS 96-row
// j-chunk, split into three rel-regions:
//   j <= i-31 : reg table s_lo  (Ptab[si]+Qtab[t]+R[62])
//   j >= i+31 : reg table s_hi  (Ptab[si]+Qtab[t]+R[0])
//   else      : smem s_mid + R[i-j+31] from L2 (<=61 rows per block)
// ---------------------------------------------------------------------------
__global__ __launch_bounds__(256, 6) void pair_kernel(const int* __restrict__ msa,
                                                      float* __restrict__ out) {
    __shared__ __align__(4) unsigned char s_seq[LSEQ];
    __shared__ float4 s_lo [5 * 32];
    __shared__ float4 s_mid[5 * 32];
    __shared__ float4 s_hi [5 * 32];

    int bx  = blockIdx.x;               // b*LSEQ + i
    int b   = (bx >= LSEQ) ? 1 : 0;
    int i   = bx - b * LSEQ;
    int tid = threadIdx.x;
    int lane = tid & 31;
    int warp = tid >> 5;

    // Load this batch's sequence (row 0 of the MSA) into shared as bytes
    const int* seq = msa + (size_t)b * N_MSA * LSEQ;
    for (int k = tid; k < LSEQ; k += 256) s_seq[k] = (unsigned char)seq[k];
    __syncthreads();

    int si = s_seq[i];

    // Build fused tables (160 threads: t = tid>>5, lane covers d as float4)
    if (tid < 5 * 32) {
        int t = tid >> 5;
        float4 p   = ((const float4*)g_Ptab)[si * 32 + lane];
        float4 q   = ((const float4*)g_Qtab)[t  * 32 + lane];
        float4 r0  = ((const float4*)g_R)[ 0 * 32 + lane];
        float4 r62 = ((const float4*)g_R)[62 * 32 + lane];
        float4 c = make_float4(p.x + q.x, p.y + q.y, p.z + q.z, p.w + q.w);
        s_mid[tid] = c;
        s_lo [tid] = make_float4(c.x + r62.x, c.y + r62.y, c.z + r62.z, c.w + r62.w);
        s_hi [tid] = make_float4(c.x + r0.x,  c.y + r0.y,  c.z + r0.z,  c.w + r0.w);
    }
    __syncthreads();

    float4* outp = (float4*)out + (size_t)bx * LSEQ * 32;
    const float4* gR4 = (const float4*)g_R;

    // This warp's contiguous chunk and its region boundaries
    int chunkBeg = warp * (LSEQ / 8);
    int chunkEnd = chunkBeg + (LSEQ / 8);
    int loEnd  = min(max(i - 30, chunkBeg), chunkEnd);   // rows with rel=62
    int midEnd = min(max(i + 31, chunkBeg), chunkEnd);   // rows with rel in (0,62)

    // lo region: register table, 4-wide batched
    run_reg(chunkBeg, loEnd, s_lo, s_seq, outp, lane);

    // mid region (<=61 rows total per block): smem table + W_pos row from L2
    for (int j = loEnd; j < midEnd; ++j) {
        int sj = s_seq[j];
        float4 c = s_mid[sj * 32 + lane];
        float4 r = __ldg(&gR4[(i - j + 31) * 32 + lane]);
        float4 v = make_float4(c.x + r.x, c.y + r.y, c.z + r.z, c.w + r.w);
        __stcs(&outp[(size_t)j * 32 + lane], v);
    }

    // hi region: register table, 4-wide batched
    run_reg(midEnd, chunkEnd, s_hi, s_seq, outp, lane);
}

extern "C" void kernel_launch(void* const* d_in, const int* in_sizes, int n_in,
                              void* d_out, int out_size) {
    const int*   msa    = (const int*)  d_in[0];  // msa_tokens (B, N_MSA, L) int32
    const float* emb    = (const float*)d_in[1];  // (5, 64)
    const float* W_proj = (const float*)d_in[2];  // (128, 128)
    const float* b_proj = (const float*)d_in[3];  // (128,)
    const float* W_pos  = (const float*)d_in[4];  // (63, 128)
    const float* b_pos  = (const float*)d_in[5];  // (128,)
    float* out = (float*)d_out;                   // (B, L, L, 128) fp32

    setup_kernel<<<5 + NREL, DM>>>(emb, W_proj, b_proj, W_pos, b_pos);
    pair_kernel<<<BATCH * LSEQ, 256>>>(msa, out);
}

// round 16
// speedup vs baseline: 1.0340x; 1.0340x over previous
#include <cuda_runtime.h>

// Problem constants (fixed by the reference setup)
#define LSEQ   768
#define BATCH  2
#define N_MSA  4
#define DM     128
#define NREL   63   // 2*MAX_LEN - 1

// Scratch tables (device globals — no allocation allowed)
__device__ float g_Ptab[5][DM];   // masked_emb[t] @ W_proj[:64, :]
__device__ float g_Qtab[5][DM];   // masked_emb[t] @ W_proj[64:, :]
__device__ float g_R[NREL][DM];   // W_pos[r] + b_proj + b_pos

// ---------------------------------------------------------------------------
// Table setup: 68 tiny blocks. Blocks 0..4 -> Ptab/Qtab row t,
// blocks 5..67 -> R row (blockIdx-5).
// ---------------------------------------------------------------------------
__global__ void setup_kernel(const float* __restrict__ emb,
                             const float* __restrict__ W_proj,
                             const float* __restrict__ b_proj,
                             const float* __restrict__ W_pos,
                             const float* __restrict__ b_pos) {
    int d = threadIdx.x;          // 0..127
    int task = blockIdx.x;
    if (task < 5) {
        int t = task;
        float pt = 0.f, qt = 0.f;
        if (t != 0) {             // token 0 is masked to zero
            #pragma unroll 16
            for (int k = 0; k < 64; k++) {
                float ek = emb[t * 64 + k];
                pt = fmaf(ek, W_proj[k * DM + d], pt);
                qt = fmaf(ek, W_proj[(64 + k) * DM + d], qt);
            }
        }
        g_Ptab[t][d] = pt;
        g_Qtab[t][d] = qt;
    } else {
        int r = task - 5;
        g_R[r][d] = W_pos[r * DM + d] + b_proj[d] + b_pos[d];
    }
}

// Select one of 5 float4 table entries by token id (0..4) with select chains.
__device__ __forceinline__ float4 sel5(int sj, float4 t0, float4 t1, float4 t2,
                                       float4 t3, float4 t4) {
    bool a = (sj < 2), b0 = (sj == 0), c2 = (sj == 2), c3 = (sj == 3);
    float4 v;
    v.x = a ? (b0 ? t0.x : t1.x) : (c2 ? t2.x : (c3 ? t3.x : t4.x));
    v.y = a ? (b0 ? t0.y : t1.y) : (c2 ? t2.y : (c3 ? t3.y : t4.y));
    v.z = a ? (b0 ? t0.z : t1.z) : (c2 ? t2.z : (c3 ? t3.z : t4.z));
    v.w = a ? (b0 ? t0.w : t1.w) : (c2 ? t2.w : (c3 ? t3.w : t4.w));
    return v;
}

// Hot loop for a saturated-rel region: table lives entirely in registers.
// Per row: 1x LDS.U8 (token) + selects + 1x STG.128 evict-first.
__device__ __forceinline__ void run_reg(int jb, int je, const float4* __restrict__ tab,
                                        const unsigned char* __restrict__ s_seq,
                                        float4* __restrict__ outp, int lane) {
    if (jb >= je) return;
    float4 t0 = tab[0 * 32 + lane];
    float4 t1 = tab[1 * 32 + lane];
    float4 t2 = tab[2 * 32 + lane];
    float4 t3 = tab[3 * 32 + lane];
    float4 t4 = tab[4 * 32 + lane];
    #pragma unroll 4
    for (int j = jb; j < je; ++j) {
        int sj = s_seq[j];                               // warp-uniform broadcast
        float4 v = sel5(sj, t0, t1, t2, t3, t4);
        __stcs(&outp[(size_t)j * 32 + lane], v);
    }
}

// ---------------------------------------------------------------------------
// Main kernel: one block per (b, i). Each warp owns a CONTIGUOUS 96-row
// j-chunk, split into three rel-regions:
//   j <= i-31 : reg table s_lo  (Ptab[si]+Qtab[t]+R[62])
//   j >= i+31 : reg table s_hi  (Ptab[si]+Qtab[t]+R[0])
//   else      : smem s_mid + R[i-j+31] from L2 (<=61 rows per block)
// ---------------------------------------------------------------------------
__global__ __launch_bounds__(256, 6) void pair_kernel(const int* __restrict__ msa,
                                                      float* __restrict__ out) {
    __shared__ unsigned char s_seq[LSEQ];
    __shared__ float4 s_lo [5 * 32];
    __shared__ float4 s_mid[5 * 32];
    __shared__ float4 s_hi [5 * 32];

    int bx  = blockIdx.x;               // b*LSEQ + i
    int b   = (bx >= LSEQ) ? 1 : 0;
    int i   = bx - b * LSEQ;
    int tid = threadIdx.x;
    int lane = tid & 31;
    int warp = tid >> 5;

    // Load this batch's sequence (row 0 of the MSA) into shared as bytes
    const int* seq = msa + (size_t)b * N_MSA * LSEQ;
    for (int k = tid; k < LSEQ; k += 256) s_seq[k] = (unsigned char)seq[k];
    __syncthreads();

    int si = s_seq[i];

    // Build fused tables (160 threads: t = tid>>5, lane covers d as float4)
    if (tid < 5 * 32) {
        int t = tid >> 5;
        float4 p   = ((const float4*)g_Ptab)[si * 32 + lane];
        float4 q   = ((const float4*)g_Qtab)[t  * 32 + lane];
        float4 r0  = ((const float4*)g_R)[ 0 * 32 + lane];
        float4 r62 = ((const float4*)g_R)[62 * 32 + lane];
        float4 c = make_float4(p.x + q.x, p.y + q.y, p.z + q.z, p.w + q.w);
        s_mid[tid] = c;
        s_lo [tid] = make_float4(c.x + r62.x, c.y + r62.y, c.z + r62.z, c.w + r62.w);
        s_hi [tid] = make_float4(c.x + r0.x,  c.y + r0.y,  c.z + r0.z,  c.w + r0.w);
    }
    __syncthreads();

    float4* outp = (float4*)out + (size_t)bx * LSEQ * 32;
    const float4* gR4 = (const float4*)g_R;

    // This warp's contiguous chunk and its region boundaries
    int chunkBeg = warp * (LSEQ / 8);
    int chunkEnd = chunkBeg + (LSEQ / 8);
    int loEnd  = min(max(i - 30, chunkBeg), chunkEnd);   // rows with rel=62
    int midEnd = min(max(i + 31, chunkBeg), chunkEnd);   // rows with rel in (0,62)

    // lo region: register table
    run_reg(chunkBeg, loEnd, s_lo, s_seq, outp, lane);

    // mid region (<=61 rows total per block): smem table + W_pos row from L2
    for (int j = loEnd; j < midEnd; ++j) {
        int sj = s_seq[j];
        float4 c = s_mid[sj * 32 + lane];
        float4 r = __ldg(&gR4[(i - j + 31) * 32 + lane]);
        float4 v = make_float4(c.x + r.x, c.y + r.y, c.z + r.z, c.w + r.w);
        __stcs(&outp[(size_t)j * 32 + lane], v);
    }

    // hi region: register table
    run_reg(midEnd, chunkEnd, s_hi, s_seq, outp, lane);
}

extern "C" void kernel_launch(void* const* d_in, const int* in_sizes, int n_in,
                              void* d_out, int out_size) {
    const int*   msa    = (const int*)  d_in[0];  // msa_tokens (B, N_MSA, L) int32
    const float* emb    = (const float*)d_in[1];  // (5, 64)
    const float* W_proj = (const float*)d_in[2];  // (128, 128)
    const float* b_proj = (const float*)d_in[3];  // (128,)
    const float* W_pos  = (const float*)d_in[4];  // (63, 128)
    const float* b_pos  = (const float*)d_in[5];  // (128,)
    float* out = (float*)d_out;                   // (B, L, L, 128) fp32

    setup_kernel<<<5 + NREL, DM>>>(emb, W_proj, b_proj, W_pos, b_pos);
    pair_kernel<<<BATCH * LSEQ, 256>>>(msa, out);
}